// round 11
// baseline (speedup 1.0000x reference)
#include <cuda_runtime.h>
#include <cuda_fp16.h>
#include <math.h>

#define R 256
#define F4 32           // 128 features = 32 float4
#define NPIX (R * R)

// Static device scratch
__device__ uint2 g_tmph[5 * (size_t)NPIX * F4];  // row-blurred levels, fp16x4 (84 MB)
__device__ uint4 g_Gt[(size_t)NPIX * 32];        // combined grid G, tf32 (33.5 MB)
__device__ uint4 g_Hh[(size_t)NPIX * 16];        // H = G@W1+b1, fp16 (16.8 MB)
__device__ uint2 g_W1p[64 * 128];                // W1 tf32 B-fragments (64 KB)

// ---------------------------------------------------------------------------
// Compile-time gaussian weights
// ---------------------------------------------------------------------------
constexpr double cexp_d(double x) {   // x <= 0
    double r = x; int k = 0;
    while (r < -0.34657359027997264) { r += 0.69314718055994530942; k++; }
    double term = 1.0, sum = 1.0;
    for (int i = 1; i < 22; i++) { term *= r / (double)i; sum += term; }
    for (int i = 0; i < k; i++) sum *= 0.5;
    return sum;
}

template <int S> struct GWt {
    float w[S];
    constexpr GWt() : w{} {
        double t[S] = {};
        double sum = 0.0;
        for (int n = 0; n < S; n++) {
            double xx = ((double)n - (double)(S - 1) * 0.5) / ((double)S * 0.5);
            t[n] = cexp_d(-0.5 * xx * xx);
            sum += t[n];
        }
        for (int n = 0; n < S; n++) w[n] = (float)(t[n] / sum);
    }
};

__device__ __forceinline__ int reflect_i(int c) {
    c = (c < 0) ? -c : c;
    return (c > R - 1) ? (2 * (R - 1) - c) : c;
}

__device__ __forceinline__ uint2 pack4(float4 v) {
    __half2 a = __floats2half2_rn(v.x, v.y);
    __half2 b = __floats2half2_rn(v.z, v.w);
    uint2 r;
    r.x = *reinterpret_cast<unsigned*>(&a);
    r.y = *reinterpret_cast<unsigned*>(&b);
    return r;
}

__device__ __forceinline__ float4 unpack4(uint2 u) {
    __half2 a = *reinterpret_cast<__half2*>(&u.x);
    __half2 b = *reinterpret_cast<__half2*>(&u.y);
    float2 fa = __half22float2(a);
    float2 fb = __half22float2(b);
    return make_float4(fa.x, fa.y, fb.x, fb.y);
}

__device__ __forceinline__ unsigned f2tf32(float f) {
    unsigned u;
    asm("cvt.rna.tf32.f32 %0, %1;" : "=r"(u) : "f"(f));
    return u;
}

__device__ __forceinline__ void mma_tf32(float* d, unsigned a0, unsigned a1,
                                         unsigned a2, unsigned a3,
                                         unsigned b0, unsigned b1) {
    asm("mma.sync.aligned.m16n8k8.row.col.f32.tf32.tf32.f32 "
        "{%0,%1,%2,%3},{%4,%5,%6,%7},{%8,%9},{%0,%1,%2,%3};"
        : "+f"(d[0]), "+f"(d[1]), "+f"(d[2]), "+f"(d[3])
        : "r"(a0), "r"(a1), "r"(a2), "r"(a3), "r"(b0), "r"(b1));
}

// ---------------------------------------------------------------------------
// W1 -> tf32 B-fragments in global
// ---------------------------------------------------------------------------
__global__ void k_w1prep(const float* __restrict__ W1) {
    int t = blockIdx.x * 256 + threadIdx.x;   // 8192
    int rr = t >> 7;
    int n  = t & 127;
    int kk = rr >> 2, tig = rr & 3;
    uint2 v;
    v.x = f2tf32(W1[(kk * 8 + tig) * 128 + n]);
    v.y = f2tf32(W1[(kk * 8 + tig + 4) * 128 + n]);
    g_W1p[rr * 128 + n] = v;
}

// ---------------------------------------------------------------------------
// Row pass (R8 exact): 512 threads, 4 rows/thread, immediate weights.
// ---------------------------------------------------------------------------
template <int S>
__device__ __forceinline__ void row_level(const float4 (*sh)[F4],
                                          int base, int f4, int lvl, int i0, int j)
{
    constexpr GWt<S> gw{};
    float4 acc[4];
#pragma unroll
    for (int q = 0; q < 4; q++) acc[q] = make_float4(0.f, 0.f, 0.f, 0.f);
#pragma unroll
    for (int r = 0; r < 4 + S - 1; r++) {
        float4 v = sh[base + 16 - S / 2 + r][f4];
#pragma unroll
        for (int q = 0; q < 4; q++) {
            int jj = r - q;
            if (jj >= 0 && jj < S) {
                float k = gw.w[jj];
                acc[q].x += k * v.x; acc[q].y += k * v.y;
                acc[q].z += k * v.z; acc[q].w += k * v.w;
            }
        }
    }
    size_t lb = (size_t)lvl * NPIX * F4;
#pragma unroll
    for (int q = 0; q < 4; q++)
        g_tmph[lb + ((size_t)(i0 + base + q) * R + j) * F4 + f4] = pack4(acc[q]);
}

__global__ void __launch_bounds__(512, 2) k_rows(const float4* __restrict__ in)
{
    __shared__ float4 sh[96][F4];
    int j  = blockIdx.x;
    int i0 = blockIdx.y * 64;
    int t  = threadIdx.x;
    int f4 = t & 31, tg = t >> 5;           // tg 0..15

    for (int rr = tg; rr < 96; rr += 16) {
        int c = reflect_i(i0 - 16 + rr);
        sh[rr][f4] = in[((size_t)c * R + j) * F4 + f4];
    }
    __syncthreads();

    int base = tg * 4;
    row_level<2 >(sh, base, f4, 0, i0, j);
    row_level<4 >(sh, base, f4, 1, i0, j);
    row_level<8 >(sh, base, f4, 2, i0, j);
    row_level<16>(sh, base, f4, 3, i0, j);
    row_level<32>(sh, base, f4, 4, i0, j);
}

// ---------------------------------------------------------------------------
// Col pass ONLY (blur accumulate incl. b0*base), writes tf32 G to global.
// Block = (row i, 64-col tile), 256 threads, 48 KB smem.
// ---------------------------------------------------------------------------
#define SMEM_C 49152

template <int S>
__device__ __forceinline__ void col_load(float4 (*sh)[F4], int lvl, int i, int j0,
                                         int f4, int tg)
{
    size_t lb = (size_t)lvl * NPIX * F4;
#pragma unroll
    for (int rr = tg; rr < 96; rr += 8) {
        int c = reflect_i(j0 - 16 + rr);
        sh[rr][f4] = unpack4(g_tmph[lb + ((size_t)i * R + c) * F4 + f4]);
    }
}

template <int S>
__device__ __forceinline__ void col_acc(const float4 (*sh)[F4],
                                        float bl, int base, int f4, float4* acc)
{
    constexpr GWt<S> gw{};
    float4 tmp[8];
#pragma unroll
    for (int q = 0; q < 8; q++) tmp[q] = make_float4(0.f, 0.f, 0.f, 0.f);
#pragma unroll
    for (int r = 0; r < 8 + S - 1; r++) {
        float4 v = sh[base + 16 - S / 2 + r][f4];
#pragma unroll
        for (int q = 0; q < 8; q++) {
            int jj = r - q;
            if (jj >= 0 && jj < S) {
                float k = gw.w[jj];
                tmp[q].x += k * v.x; tmp[q].y += k * v.y;
                tmp[q].z += k * v.z; tmp[q].w += k * v.w;
            }
        }
    }
#pragma unroll
    for (int q = 0; q < 8; q++) {
        acc[q].x += bl * tmp[q].x; acc[q].y += bl * tmp[q].y;
        acc[q].z += bl * tmp[q].z; acc[q].w += bl * tmp[q].w;
    }
}

__global__ void __launch_bounds__(256) k_cols(const float4* __restrict__ base4,
                                              const float* __restrict__ b_levels)
{
    extern __shared__ unsigned char smem_raw[];
    float4 (*sh)[F4] = (float4 (*)[F4])smem_raw;

    int i  = blockIdx.x;
    int j0 = blockIdx.y * 64;
    int t  = threadIdx.x;
    int f4 = t & 31, tg = t >> 5;
    int base = tg * 8;

    float b0 = b_levels[0];
    float4 acc[8];
#pragma unroll
    for (int q = 0; q < 8; q++) {
        float4 v = base4[((size_t)i * R + (j0 + base + q)) * F4 + f4];
        acc[q] = make_float4(b0 * v.x, b0 * v.y, b0 * v.z, b0 * v.w);
    }

    col_load<2 >(sh, 0, i, j0, f4, tg); __syncthreads();
    col_acc <2 >(sh, b_levels[1], base, f4, acc); __syncthreads();
    col_load<4 >(sh, 1, i, j0, f4, tg); __syncthreads();
    col_acc <4 >(sh, b_levels[2], base, f4, acc); __syncthreads();
    col_load<8 >(sh, 2, i, j0, f4, tg); __syncthreads();
    col_acc <8 >(sh, b_levels[3], base, f4, acc); __syncthreads();
    col_load<16>(sh, 3, i, j0, f4, tg); __syncthreads();
    col_acc <16>(sh, b_levels[4], base, f4, acc); __syncthreads();
    col_load<32>(sh, 4, i, j0, f4, tg); __syncthreads();
    col_acc <32>(sh, b_levels[5], base, f4, acc);

    // Write G as tf32 (coalesced uint4)
#pragma unroll
    for (int q = 0; q < 8; q++) {
        uint4 u;
        u.x = f2tf32(acc[q].x); u.y = f2tf32(acc[q].y);
        u.z = f2tf32(acc[q].z); u.w = f2tf32(acc[q].w);
        g_Gt[((size_t)i * R + (j0 + base + q)) * 32 + f4] = u;
    }
}

// ---------------------------------------------------------------------------
// H = G @ W1 + b1 via tf32 MMA. Block = 128 pixels, 512 threads / 16 warps.
// smem: Gs uint[128*132] = 67584 (reused as Hs half2[128][68]); b1s @67584.
// ---------------------------------------------------------------------------
#define SMEM_H 68096

__global__ void __launch_bounds__(512) k_H(const float* __restrict__ b1)
{
    extern __shared__ unsigned char smem_raw[];
    unsigned* Gs  = (unsigned*)smem_raw;
    float*    b1s = (float*)(smem_raw + 67584);

    int blk = blockIdx.x;          // 512 blocks x 128 pixels
    int t   = threadIdx.x;

    // Stage G tile (row stride 132 words; conflict-free MMA A-reads)
#pragma unroll
    for (int it = 0; it < 8; it++) {
        int task = it * 512 + t;
        int p  = task >> 5;
        int q4 = task & 31;
        uint4 v = g_Gt[((size_t)blk * 128 + p) * 32 + q4];
        *reinterpret_cast<uint4*>(&Gs[p * 132 + 4 * q4]) = v;
    }
    if (t < 128) b1s[t] = b1[t];
    __syncthreads();

    // MMA: 128x128 = 8 m-tiles x 2 n-halves. warp = (mt = w&7, nh = w>>3).
    int w    = t >> 5;
    int lane = t & 31;
    int mt   = w & 7;
    int nh   = w >> 3;
    int g    = lane >> 2;
    int tig  = lane & 3;

    float d[8][4];
#pragma unroll
    for (int nt = 0; nt < 8; nt++)
#pragma unroll
        for (int e = 0; e < 4; e++) d[nt][e] = 0.0f;

#pragma unroll 4
    for (int kk = 0; kk < 16; kk++) {
        int arow = (mt * 16 + g) * 132 + kk * 8 + tig;
        unsigned a0 = Gs[arow];
        unsigned a1 = Gs[arow + 8 * 132];
        unsigned a2 = Gs[arow + 4];
        unsigned a3 = Gs[arow + 8 * 132 + 4];
        int brow = (kk * 4 + tig) * 128 + nh * 64 + g;
#pragma unroll
        for (int nt = 0; nt < 8; nt++) {
            uint2 b = g_W1p[brow + nt * 8];
            mma_tf32(d[nt], a0, a1, a2, a3, b.x, b.y);
        }
    }
    __syncthreads();   // all Gs reads done -> reuse as Hs

    __half2* Hs2 = (__half2*)smem_raw;   // [128][68]
    int m0 = mt * 16 + g;
#pragma unroll
    for (int nt = 0; nt < 8; nt++) {
        int n0 = nh * 64 + nt * 8 + 2 * tig;
        float bb0 = b1s[n0], bb1 = b1s[n0 + 1];
        Hs2[m0 * 68 + (n0 >> 1)]       = __floats2half2_rn(d[nt][0] + bb0,
                                                           d[nt][1] + bb1);
        Hs2[(m0 + 8) * 68 + (n0 >> 1)] = __floats2half2_rn(d[nt][2] + bb0,
                                                           d[nt][3] + bb1);
    }
    __syncthreads();

    // Coalesced fp16 H store: 128 pixels x 16 uint4 (row stride 17 uint4)
    const uint4* Hs4 = (const uint4*)smem_raw;
#pragma unroll
    for (int it = 0; it < 4; it++) {
        int task = it * 512 + t;
        int p  = task >> 4;
        int q4 = task & 15;
        g_Hh[((size_t)blk * 128 + p) * 16 + q4] = Hs4[p * 17 + q4];
    }
}

// ---------------------------------------------------------------------------
// Points: bilerp gather of fp16 H + relu + W2 + b2.  (R8 exact)
// ---------------------------------------------------------------------------
__global__ void __launch_bounds__(256) k_pts(const float* __restrict__ pt,
                                             const float4* __restrict__ W2v,
                                             const float* __restrict__ b2,
                                             float4* __restrict__ out4)
{
    int t = threadIdx.x, lane = t & 31, w = t >> 5;
    int lh = lane >> 4;
    int lf = lane & 15;

    float4 w2r[8];
#pragma unroll
    for (int j = 0; j < 8; j++) w2r[j] = W2v[lf * 8 + j];
    float b20 = b2[0], b21 = b2[1], b22 = b2[2], b23 = b2[3];

    int p0 = blockIdx.x * 128 + w * 16 + lh;
#pragma unroll 2
    for (int it = 0; it < 8; it++) {
        int p = p0 + it * 2;
        float px = pt[2 * p];
        float py = pt[2 * p + 1];
        float ax = (px + 1.0f) / 2.0f * 255.0f;
        float ay = (py + 1.0f) / 2.0f * 255.0f;
        int ix = (int)ax; if (ix > 255) ix = 255;
        int iy = (int)ay; if (iy > 255) iy = 255;
        float fx = ax - (float)ix;
        float fy = ay - (float)iy;
        int ix1 = (ix + 1 > 255) ? 255 : ix + 1;
        int iy1 = (iy + 1 > 255) ? 255 : iy + 1;
        float w00 = (1.0f - fx) * (1.0f - fy);
        float w01 = (1.0f - fx) * fy;
        float w10 = fx * (1.0f - fy);
        float w11 = fx * fy;

        uint4 c00 = g_Hh[((size_t)(ix  * R + iy )) * 16 + lf];
        uint4 c01 = g_Hh[((size_t)(ix  * R + iy1)) * 16 + lf];
        uint4 c10 = g_Hh[((size_t)(ix1 * R + iy )) * 16 + lf];
        uint4 c11 = g_Hh[((size_t)(ix1 * R + iy1)) * 16 + lf];

        float v[8];
#pragma unroll
        for (int k = 0; k < 8; k++) v[k] = 0.0f;
        {
            const unsigned* cs[4] = {&c00.x, &c01.x, &c10.x, &c11.x};
            float ws[4] = {w00, w01, w10, w11};
#pragma unroll
            for (int cc = 0; cc < 4; cc++) {
                float wgt = ws[cc];
#pragma unroll
                for (int k = 0; k < 4; k++) {
                    __half2 h = *reinterpret_cast<const __half2*>(&cs[cc][k]);
                    float2 f = __half22float2(h);
                    v[2 * k]     += wgt * f.x;
                    v[2 * k + 1] += wgt * f.y;
                }
            }
        }

        float4 o = make_float4(0.f, 0.f, 0.f, 0.f);
#pragma unroll
        for (int j = 0; j < 8; j++) {
            float h = fmaxf(v[j], 0.0f);
            o.x += h * w2r[j].x; o.y += h * w2r[j].y;
            o.z += h * w2r[j].z; o.w += h * w2r[j].w;
        }

#pragma unroll
        for (int off = 8; off; off >>= 1) {
            o.x += __shfl_xor_sync(0xffffffffu, o.x, off);
            o.y += __shfl_xor_sync(0xffffffffu, o.y, off);
            o.z += __shfl_xor_sync(0xffffffffu, o.z, off);
            o.w += __shfl_xor_sync(0xffffffffu, o.w, off);
        }
        if (lf == 0)
            out4[p] = make_float4(o.x + b20, o.y + b21, o.z + b22, o.w + b23);
    }
}

// ---------------------------------------------------------------------------
extern "C" void kernel_launch(void* const* d_in, const int* in_sizes, int n_in,
                              void* d_out, int out_size) {
    const float*  pt       = (const float*)d_in[0];
    const float4* base4    = (const float4*)d_in[1];
    const float*  b_levels = (const float*)d_in[2];
    const float*  W1       = (const float*)d_in[3];
    const float*  b1       = (const float*)d_in[4];
    const float*  W2       = (const float*)d_in[5];
    const float*  b2       = (const float*)d_in[6];
    float* out             = (float*)d_out;

    cudaFuncSetAttribute(k_cols, cudaFuncAttributeMaxDynamicSharedMemorySize,
                         SMEM_C);
    cudaFuncSetAttribute(k_H, cudaFuncAttributeMaxDynamicSharedMemorySize,
                         SMEM_H);

    k_w1prep<<<32, 256>>>(W1);

    dim3 bg(256, 4);
    k_rows<<<bg, 512>>>(base4);
    k_cols<<<bg, 256, SMEM_C>>>(base4, b_levels);
    k_H<<<512, 512, SMEM_H>>>(b1);
    k_pts<<<2048, 256>>>(pt, (const float4*)W2, b2, (float4*)out);
}

// round 12
// speedup vs baseline: 1.3078x; 1.3078x over previous
#include <cuda_runtime.h>
#include <cuda_fp16.h>
#include <math.h>

#define R 256
#define F4 32           // 128 features = 32 float4
#define NPIX (R * R)

// Static device scratch
__device__ uint2 g_tmph[5 * (size_t)NPIX * F4];  // row-blurred levels, fp16x4 (84 MB)
__device__ uint4 g_Gt[(size_t)NPIX * 32];        // combined grid G, tf32 (33.5 MB)
__device__ uint4 g_Hh[(size_t)NPIX * 16];        // H = G@W1+b1, fp16 (16.8 MB)
__device__ uint2 g_W1p[64 * 128];                // W1 tf32 B-fragments (64 KB)

// ---------------------------------------------------------------------------
// Compile-time gaussian weights
// ---------------------------------------------------------------------------
constexpr double cexp_d(double x) {   // x <= 0
    double r = x; int k = 0;
    while (r < -0.34657359027997264) { r += 0.69314718055994530942; k++; }
    double term = 1.0, sum = 1.0;
    for (int i = 1; i < 22; i++) { term *= r / (double)i; sum += term; }
    for (int i = 0; i < k; i++) sum *= 0.5;
    return sum;
}

template <int S> struct GWt {
    float w[S];
    constexpr GWt() : w{} {
        double t[S] = {};
        double sum = 0.0;
        for (int n = 0; n < S; n++) {
            double xx = ((double)n - (double)(S - 1) * 0.5) / ((double)S * 0.5);
            t[n] = cexp_d(-0.5 * xx * xx);
            sum += t[n];
        }
        for (int n = 0; n < S; n++) w[n] = (float)(t[n] / sum);
    }
};

__device__ __forceinline__ int reflect_i(int c) {
    c = (c < 0) ? -c : c;
    return (c > R - 1) ? (2 * (R - 1) - c) : c;
}

__device__ __forceinline__ uint2 pack4(float4 v) {
    __half2 a = __floats2half2_rn(v.x, v.y);
    __half2 b = __floats2half2_rn(v.z, v.w);
    uint2 r;
    r.x = *reinterpret_cast<unsigned*>(&a);
    r.y = *reinterpret_cast<unsigned*>(&b);
    return r;
}

__device__ __forceinline__ float4 unpack4(uint2 u) {
    __half2 a = *reinterpret_cast<__half2*>(&u.x);
    __half2 b = *reinterpret_cast<__half2*>(&u.y);
    float2 fa = __half22float2(a);
    float2 fb = __half22float2(b);
    return make_float4(fa.x, fa.y, fb.x, fb.y);
}

__device__ __forceinline__ unsigned f2tf32(float f) {
    unsigned u;
    asm("cvt.rna.tf32.f32 %0, %1;" : "=r"(u) : "f"(f));
    return u;
}

__device__ __forceinline__ unsigned smem_u32(const void* p) {
    unsigned a;
    asm("{ .reg .u64 t; cvta.to.shared.u64 t, %1; cvt.u32.u64 %0, t; }"
        : "=r"(a) : "l"(p));
    return a;
}

__device__ __forceinline__ void mma_tf32(float* d, unsigned a0, unsigned a1,
                                         unsigned a2, unsigned a3,
                                         unsigned b0, unsigned b1) {
    asm("mma.sync.aligned.m16n8k8.row.col.f32.tf32.tf32.f32 "
        "{%0,%1,%2,%3},{%4,%5,%6,%7},{%8,%9},{%0,%1,%2,%3};"
        : "+f"(d[0]), "+f"(d[1]), "+f"(d[2]), "+f"(d[3])
        : "r"(a0), "r"(a1), "r"(a2), "r"(a3), "r"(b0), "r"(b1));
}

// ---------------------------------------------------------------------------
// W1 -> tf32 B-fragments in global
// ---------------------------------------------------------------------------
__global__ void k_w1prep(const float* __restrict__ W1) {
    int t = blockIdx.x * 256 + threadIdx.x;   // 8192
    int rr = t >> 7;
    int n  = t & 127;
    int kk = rr >> 2, tig = rr & 3;
    uint2 v;
    v.x = f2tf32(W1[(kk * 8 + tig) * 128 + n]);
    v.y = f2tf32(W1[(kk * 8 + tig + 4) * 128 + n]);
    g_W1p[rr * 128 + n] = v;
}

// ---------------------------------------------------------------------------
// Row pass (R8 exact): 512 threads, 4 rows/thread, immediate weights.
// ---------------------------------------------------------------------------
template <int S>
__device__ __forceinline__ void row_level(const float4 (*sh)[F4],
                                          int base, int f4, int lvl, int i0, int j)
{
    constexpr GWt<S> gw{};
    float4 acc[4];
#pragma unroll
    for (int q = 0; q < 4; q++) acc[q] = make_float4(0.f, 0.f, 0.f, 0.f);
#pragma unroll
    for (int r = 0; r < 4 + S - 1; r++) {
        float4 v = sh[base + 16 - S / 2 + r][f4];
#pragma unroll
        for (int q = 0; q < 4; q++) {
            int jj = r - q;
            if (jj >= 0 && jj < S) {
                float k = gw.w[jj];
                acc[q].x += k * v.x; acc[q].y += k * v.y;
                acc[q].z += k * v.z; acc[q].w += k * v.w;
            }
        }
    }
    size_t lb = (size_t)lvl * NPIX * F4;
#pragma unroll
    for (int q = 0; q < 4; q++)
        g_tmph[lb + ((size_t)(i0 + base + q) * R + j) * F4 + f4] = pack4(acc[q]);
}

__global__ void __launch_bounds__(512, 2) k_rows(const float4* __restrict__ in)
{
    __shared__ float4 sh[96][F4];
    int j  = blockIdx.x;
    int i0 = blockIdx.y * 64;
    int t  = threadIdx.x;
    int f4 = t & 31, tg = t >> 5;           // tg 0..15

    for (int rr = tg; rr < 96; rr += 16) {
        int c = reflect_i(i0 - 16 + rr);
        sh[rr][f4] = in[((size_t)c * R + j) * F4 + f4];
    }
    __syncthreads();

    int base = tg * 4;
    row_level<2 >(sh, base, f4, 0, i0, j);
    row_level<4 >(sh, base, f4, 1, i0, j);
    row_level<8 >(sh, base, f4, 2, i0, j);
    row_level<16>(sh, base, f4, 3, i0, j);
    row_level<32>(sh, base, f4, 4, i0, j);
}

// ---------------------------------------------------------------------------
// Col pass, cp.async double-buffered fp16 staging. Block = (row i, 64 cols),
// 256 threads. smem: shA uint2[96][32] 24576 @0, shB @24576. total 49152.
// ---------------------------------------------------------------------------
#define SMEM_C 49152

__device__ __forceinline__ void issue_level(uint2* buf, int lvl, int i, int j0,
                                            int f4, int tg)
{
    size_t lb = (size_t)lvl * NPIX * F4 + (size_t)i * R * F4;
#pragma unroll
    for (int rr = tg; rr < 96; rr += 8) {
        int c = reflect_i(j0 - 16 + rr);
        unsigned dst = smem_u32(&buf[rr * 32 + f4]);
        const uint2* src = &g_tmph[lb + (size_t)c * F4 + f4];
        asm volatile("cp.async.ca.shared.global [%0], [%1], 8;"
                     :: "r"(dst), "l"(src) : "memory");
    }
    asm volatile("cp.async.commit_group;" ::: "memory");
}

template <int S>
__device__ __forceinline__ void col_acc(const uint2* __restrict__ buf,
                                        float bl, int base, int f4, float4* acc)
{
    constexpr GWt<S> gw{};
    float4 tmp[8];
#pragma unroll
    for (int q = 0; q < 8; q++) tmp[q] = make_float4(0.f, 0.f, 0.f, 0.f);
#pragma unroll
    for (int r = 0; r < 8 + S - 1; r++) {
        float4 v = unpack4(buf[(base + 16 - S / 2 + r) * 32 + f4]);
#pragma unroll
        for (int q = 0; q < 8; q++) {
            int jj = r - q;
            if (jj >= 0 && jj < S) {
                float k = gw.w[jj];
                tmp[q].x += k * v.x; tmp[q].y += k * v.y;
                tmp[q].z += k * v.z; tmp[q].w += k * v.w;
            }
        }
    }
#pragma unroll
    for (int q = 0; q < 8; q++) {
        acc[q].x += bl * tmp[q].x; acc[q].y += bl * tmp[q].y;
        acc[q].z += bl * tmp[q].z; acc[q].w += bl * tmp[q].w;
    }
}

__global__ void __launch_bounds__(256) k_cols(const float4* __restrict__ base4,
                                              const float* __restrict__ b_levels)
{
    extern __shared__ unsigned char smem_raw[];
    uint2* shA = (uint2*)smem_raw;             // [96][32] fp16x4
    uint2* shB = (uint2*)(smem_raw + 24576);

    int i  = blockIdx.x;
    int j0 = blockIdx.y * 64;
    int t  = threadIdx.x;
    int f4 = t & 31, tg = t >> 5;
    int base = tg * 8;

    issue_level(shA, 0, i, j0, f4, tg);        // level S=2 -> A

    float b0 = b_levels[0];
    float4 acc[8];
#pragma unroll
    for (int q = 0; q < 8; q++) {
        float4 v = base4[((size_t)i * R + (j0 + base + q)) * F4 + f4];
        acc[q] = make_float4(b0 * v.x, b0 * v.y, b0 * v.z, b0 * v.w);
    }

    issue_level(shB, 1, i, j0, f4, tg);        // S=4 -> B
    asm volatile("cp.async.wait_group 1;" ::: "memory");
    __syncthreads();
    col_acc<2 >(shA, b_levels[1], base, f4, acc);
    __syncthreads();

    issue_level(shA, 2, i, j0, f4, tg);        // S=8 -> A
    asm volatile("cp.async.wait_group 1;" ::: "memory");
    __syncthreads();
    col_acc<4 >(shB, b_levels[2], base, f4, acc);
    __syncthreads();

    issue_level(shB, 3, i, j0, f4, tg);        // S=16 -> B
    asm volatile("cp.async.wait_group 1;" ::: "memory");
    __syncthreads();
    col_acc<8 >(shA, b_levels[3], base, f4, acc);
    __syncthreads();

    issue_level(shA, 4, i, j0, f4, tg);        // S=32 -> A
    asm volatile("cp.async.wait_group 1;" ::: "memory");
    __syncthreads();
    col_acc<16>(shB, b_levels[4], base, f4, acc);
    __syncthreads();

    asm volatile("cp.async.wait_group 0;" ::: "memory");
    __syncthreads();
    col_acc<32>(shA, b_levels[5], base, f4, acc);

    // Write G as tf32 (coalesced uint4)
#pragma unroll
    for (int q = 0; q < 8; q++) {
        uint4 u;
        u.x = f2tf32(acc[q].x); u.y = f2tf32(acc[q].y);
        u.z = f2tf32(acc[q].z); u.w = f2tf32(acc[q].w);
        g_Gt[((size_t)i * R + (j0 + base + q)) * 32 + f4] = u;
    }
}

// ---------------------------------------------------------------------------
// H = G @ W1 + b1 via tf32 MMA, W1 fragments smem-resident.
// Block = 128 pixels, 512 threads / 16 warps.
// smem: Gs uint[128*132] 67584 @0 (reused as Hs); W1s uint2[64*132] @67584;
//       b1s @135168. total 135680.
// ---------------------------------------------------------------------------
#define SMEM_H 135680

__global__ void __launch_bounds__(512) k_H(const float* __restrict__ b1)
{
    extern __shared__ unsigned char smem_raw[];
    unsigned* Gs  = (unsigned*)smem_raw;
    uint2*    W1s = (uint2*)(smem_raw + 67584);
    float*    b1s = (float*)(smem_raw + 135168);

    int blk = blockIdx.x;          // 512 blocks x 128 pixels
    int t   = threadIdx.x;

    // Stage W1 fragments (stride 132 for conflict-free LDS)
#pragma unroll
    for (int it = 0; it < 16; it++) {
        int task = it * 512 + t;
        int r = task >> 7;
        int n = task & 127;
        W1s[r * 132 + n] = g_W1p[r * 128 + n];
    }
    // Stage G tile (row stride 132 words)
#pragma unroll
    for (int it = 0; it < 8; it++) {
        int task = it * 512 + t;
        int p  = task >> 5;
        int q4 = task & 31;
        uint4 v = g_Gt[((size_t)blk * 128 + p) * 32 + q4];
        *reinterpret_cast<uint4*>(&Gs[p * 132 + 4 * q4]) = v;
    }
    if (t < 128) b1s[t] = b1[t];
    __syncthreads();

    // MMA: 128x128 = 8 m-tiles x 2 n-halves. warp = (mt = w&7, nh = w>>3).
    int w    = t >> 5;
    int lane = t & 31;
    int mt   = w & 7;
    int nh   = w >> 3;
    int g    = lane >> 2;
    int tig  = lane & 3;

    float d[8][4];
#pragma unroll
    for (int nt = 0; nt < 8; nt++)
#pragma unroll
        for (int e = 0; e < 4; e++) d[nt][e] = 0.0f;

#pragma unroll 4
    for (int kk = 0; kk < 16; kk++) {
        int arow = (mt * 16 + g) * 132 + kk * 8 + tig;
        unsigned a0 = Gs[arow];
        unsigned a1 = Gs[arow + 8 * 132];
        unsigned a2 = Gs[arow + 4];
        unsigned a3 = Gs[arow + 8 * 132 + 4];
        int brow = (kk * 4 + tig) * 132 + nh * 64 + g;
#pragma unroll
        for (int nt = 0; nt < 8; nt++) {
            uint2 b = W1s[brow + nt * 8];
            mma_tf32(d[nt], a0, a1, a2, a3, b.x, b.y);
        }
    }
    __syncthreads();   // all Gs reads done -> reuse as Hs

    __half2* Hs2 = (__half2*)smem_raw;   // [128][68]
    int m0 = mt * 16 + g;
#pragma unroll
    for (int nt = 0; nt < 8; nt++) {
        int n0 = nh * 64 + nt * 8 + 2 * tig;
        float bb0 = b1s[n0], bb1 = b1s[n0 + 1];
        Hs2[m0 * 68 + (n0 >> 1)]       = __floats2half2_rn(d[nt][0] + bb0,
                                                           d[nt][1] + bb1);
        Hs2[(m0 + 8) * 68 + (n0 >> 1)] = __floats2half2_rn(d[nt][2] + bb0,
                                                           d[nt][3] + bb1);
    }
    __syncthreads();

    // Coalesced fp16 H store: 128 pixels x 16 uint4 (row stride 17 uint4)
    const uint4* Hs4 = (const uint4*)smem_raw;
#pragma unroll
    for (int it = 0; it < 4; it++) {
        int task = it * 512 + t;
        int p  = task >> 4;
        int q4 = task & 15;
        g_Hh[((size_t)blk * 128 + p) * 16 + q4] = Hs4[p * 17 + q4];
    }
}

// ---------------------------------------------------------------------------
// Points: bilerp gather of fp16 H + relu + W2 + b2.  (R8 exact)
// ---------------------------------------------------------------------------
__global__ void __launch_bounds__(256) k_pts(const float* __restrict__ pt,
                                             const float4* __restrict__ W2v,
                                             const float* __restrict__ b2,
                                             float4* __restrict__ out4)
{
    int t = threadIdx.x, lane = t & 31, w = t >> 5;
    int lh = lane >> 4;
    int lf = lane & 15;

    float4 w2r[8];
#pragma unroll
    for (int j = 0; j < 8; j++) w2r[j] = W2v[lf * 8 + j];
    float b20 = b2[0], b21 = b2[1], b22 = b2[2], b23 = b2[3];

    int p0 = blockIdx.x * 128 + w * 16 + lh;
#pragma unroll 2
    for (int it = 0; it < 8; it++) {
        int p = p0 + it * 2;
        float px = pt[2 * p];
        float py = pt[2 * p + 1];
        float ax = (px + 1.0f) / 2.0f * 255.0f;
        float ay = (py + 1.0f) / 2.0f * 255.0f;
        int ix = (int)ax; if (ix > 255) ix = 255;
        int iy = (int)ay; if (iy > 255) iy = 255;
        float fx = ax - (float)ix;
        float fy = ay - (float)iy;
        int ix1 = (ix + 1 > 255) ? 255 : ix + 1;
        int iy1 = (iy + 1 > 255) ? 255 : iy + 1;
        float w00 = (1.0f - fx) * (1.0f - fy);
        float w01 = (1.0f - fx) * fy;
        float w10 = fx * (1.0f - fy);
        float w11 = fx * fy;

        uint4 c00 = g_Hh[((size_t)(ix  * R + iy )) * 16 + lf];
        uint4 c01 = g_Hh[((size_t)(ix  * R + iy1)) * 16 + lf];
        uint4 c10 = g_Hh[((size_t)(ix1 * R + iy )) * 16 + lf];
        uint4 c11 = g_Hh[((size_t)(ix1 * R + iy1)) * 16 + lf];

        float v[8];
#pragma unroll
        for (int k = 0; k < 8; k++) v[k] = 0.0f;
        {
            const unsigned* cs[4] = {&c00.x, &c01.x, &c10.x, &c11.x};
            float ws[4] = {w00, w01, w10, w11};
#pragma unroll
            for (int cc = 0; cc < 4; cc++) {
                float wgt = ws[cc];
#pragma unroll
                for (int k = 0; k < 4; k++) {
                    __half2 h = *reinterpret_cast<const __half2*>(&cs[cc][k]);
                    float2 f = __half22float2(h);
                    v[2 * k]     += wgt * f.x;
                    v[2 * k + 1] += wgt * f.y;
                }
            }
        }

        float4 o = make_float4(0.f, 0.f, 0.f, 0.f);
#pragma unroll
        for (int j = 0; j < 8; j++) {
            float h = fmaxf(v[j], 0.0f);
            o.x += h * w2r[j].x; o.y += h * w2r[j].y;
            o.z += h * w2r[j].z; o.w += h * w2r[j].w;
        }

#pragma unroll
        for (int off = 8; off; off >>= 1) {
            o.x += __shfl_xor_sync(0xffffffffu, o.x, off);
            o.y += __shfl_xor_sync(0xffffffffu, o.y, off);
            o.z += __shfl_xor_sync(0xffffffffu, o.z, off);
            o.w += __shfl_xor_sync(0xffffffffu, o.w, off);
        }
        if (lf == 0)
            out4[p] = make_float4(o.x + b20, o.y + b21, o.z + b22, o.w + b23);
    }
}

// ---------------------------------------------------------------------------
extern "C" void kernel_launch(void* const* d_in, const int* in_sizes, int n_in,
                              void* d_out, int out_size) {
    const float*  pt       = (const float*)d_in[0];
    const float4* base4    = (const float4*)d_in[1];
    const float*  b_levels = (const float*)d_in[2];
    const float*  W1       = (const float*)d_in[3];
    const float*  b1       = (const float*)d_in[4];
    const float*  W2       = (const float*)d_in[5];
    const float*  b2       = (const float*)d_in[6];
    float* out             = (float*)d_out;

    cudaFuncSetAttribute(k_cols, cudaFuncAttributeMaxDynamicSharedMemorySize,
                         SMEM_C);
    cudaFuncSetAttribute(k_H, cudaFuncAttributeMaxDynamicSharedMemorySize,
                         SMEM_H);

    k_w1prep<<<32, 256>>>(W1);

    dim3 bg(256, 4);
    k_rows<<<bg, 512>>>(base4);
    k_cols<<<bg, 256, SMEM_C>>>(base4, b_levels);
    k_H<<<512, 512, SMEM_H>>>(b1);
    k_pts<<<2048, 256>>>(pt, (const float4*)W2, b2, (float4*)out);
}

// round 13
// speedup vs baseline: 1.4652x; 1.1203x over previous
#include <cuda_runtime.h>
#include <cuda_fp16.h>
#include <math.h>

#define R 256
#define F4 32           // 128 features = 32 float4
#define NPIX (R * R)

// Static device scratch
__device__ uint2 g_tmph[5 * (size_t)NPIX * F4];  // row-blurred levels, fp16x4 (84 MB)
__device__ uint2 g_Gh[(size_t)NPIX * 32];        // combined grid G, fp16 (16.8 MB)
__device__ uint4 g_Hh[(size_t)NPIX * 16];        // H = G@W1+b1, fp16 (16.8 MB)
__device__ uint2 g_W1h[32 * 128];                // W1 fp16 B-fragments (32 KB)

// ---------------------------------------------------------------------------
// Compile-time gaussian weights
// ---------------------------------------------------------------------------
constexpr double cexp_d(double x) {   // x <= 0
    double r = x; int k = 0;
    while (r < -0.34657359027997264) { r += 0.69314718055994530942; k++; }
    double term = 1.0, sum = 1.0;
    for (int i = 1; i < 22; i++) { term *= r / (double)i; sum += term; }
    for (int i = 0; i < k; i++) sum *= 0.5;
    return sum;
}

template <int S> struct GWt {
    float w[S];
    constexpr GWt() : w{} {
        double t[S] = {};
        double sum = 0.0;
        for (int n = 0; n < S; n++) {
            double xx = ((double)n - (double)(S - 1) * 0.5) / ((double)S * 0.5);
            t[n] = cexp_d(-0.5 * xx * xx);
            sum += t[n];
        }
        for (int n = 0; n < S; n++) w[n] = (float)(t[n] / sum);
    }
};

__device__ __forceinline__ int reflect_i(int c) {
    c = (c < 0) ? -c : c;
    return (c > R - 1) ? (2 * (R - 1) - c) : c;
}

__device__ __forceinline__ uint2 pack4(float4 v) {
    __half2 a = __floats2half2_rn(v.x, v.y);
    __half2 b = __floats2half2_rn(v.z, v.w);
    uint2 r;
    r.x = *reinterpret_cast<unsigned*>(&a);
    r.y = *reinterpret_cast<unsigned*>(&b);
    return r;
}

__device__ __forceinline__ float4 unpack4(uint2 u) {
    __half2 a = *reinterpret_cast<__half2*>(&u.x);
    __half2 b = *reinterpret_cast<__half2*>(&u.y);
    float2 fa = __half22float2(a);
    float2 fb = __half22float2(b);
    return make_float4(fa.x, fa.y, fb.x, fb.y);
}

__device__ __forceinline__ unsigned smem_u32(const void* p) {
    unsigned a;
    asm("{ .reg .u64 t; cvta.to.shared.u64 t, %1; cvt.u32.u64 %0, t; }"
        : "=r"(a) : "l"(p));
    return a;
}

// fp16 MMA m16n8k16, fp32 accum
__device__ __forceinline__ void mma_f16(float* d, unsigned a0, unsigned a1,
                                        unsigned a2, unsigned a3,
                                        unsigned b0, unsigned b1) {
    asm("mma.sync.aligned.m16n8k16.row.col.f32.f16.f16.f32 "
        "{%0,%1,%2,%3},{%4,%5,%6,%7},{%8,%9},{%0,%1,%2,%3};"
        : "+f"(d[0]), "+f"(d[1]), "+f"(d[2]), "+f"(d[3])
        : "r"(a0), "r"(a1), "r"(a2), "r"(a3), "r"(b0), "r"(b1));
}

// ---------------------------------------------------------------------------
// W1 -> fp16 B-fragments: g_W1h[(kk*4+tig)*128 + n] =
//   { h2(W1[16kk+2tig][n], W1[16kk+2tig+1][n]),
//     h2(W1[16kk+2tig+8][n], W1[16kk+2tig+9][n]) }
// ---------------------------------------------------------------------------
__global__ void k_w1prep(const float* __restrict__ W1) {
    int t = blockIdx.x * 256 + threadIdx.x;   // 4096
    int rr = t >> 7;        // 0..31
    int n  = t & 127;
    int kk = rr >> 2, tig = rr & 3;
    int k0 = kk * 16 + 2 * tig;
    __half2 lo = __floats2half2_rn(W1[k0 * 128 + n],       W1[(k0 + 1) * 128 + n]);
    __half2 hi = __floats2half2_rn(W1[(k0 + 8) * 128 + n], W1[(k0 + 9) * 128 + n]);
    uint2 v;
    v.x = *reinterpret_cast<unsigned*>(&lo);
    v.y = *reinterpret_cast<unsigned*>(&hi);
    g_W1h[rr * 128 + n] = v;
}

// ---------------------------------------------------------------------------
// Row pass (R8/R12 exact): 512 threads, 4 rows/thread, immediate weights.
// ---------------------------------------------------------------------------
template <int S>
__device__ __forceinline__ void row_level(const float4 (*sh)[F4],
                                          int base, int f4, int lvl, int i0, int j)
{
    constexpr GWt<S> gw{};
    float4 acc[4];
#pragma unroll
    for (int q = 0; q < 4; q++) acc[q] = make_float4(0.f, 0.f, 0.f, 0.f);
#pragma unroll
    for (int r = 0; r < 4 + S - 1; r++) {
        float4 v = sh[base + 16 - S / 2 + r][f4];
#pragma unroll
        for (int q = 0; q < 4; q++) {
            int jj = r - q;
            if (jj >= 0 && jj < S) {
                float k = gw.w[jj];
                acc[q].x += k * v.x; acc[q].y += k * v.y;
                acc[q].z += k * v.z; acc[q].w += k * v.w;
            }
        }
    }
    size_t lb = (size_t)lvl * NPIX * F4;
#pragma unroll
    for (int q = 0; q < 4; q++)
        g_tmph[lb + ((size_t)(i0 + base + q) * R + j) * F4 + f4] = pack4(acc[q]);
}

__global__ void __launch_bounds__(512, 2) k_rows(const float4* __restrict__ in)
{
    __shared__ float4 sh[96][F4];
    int j  = blockIdx.x;
    int i0 = blockIdx.y * 64;
    int t  = threadIdx.x;
    int f4 = t & 31, tg = t >> 5;           // tg 0..15

    for (int rr = tg; rr < 96; rr += 16) {
        int c = reflect_i(i0 - 16 + rr);
        sh[rr][f4] = in[((size_t)c * R + j) * F4 + f4];
    }
    __syncthreads();

    int base = tg * 4;
    row_level<2 >(sh, base, f4, 0, i0, j);
    row_level<4 >(sh, base, f4, 1, i0, j);
    row_level<8 >(sh, base, f4, 2, i0, j);
    row_level<16>(sh, base, f4, 3, i0, j);
    row_level<32>(sh, base, f4, 4, i0, j);
}

// ---------------------------------------------------------------------------
// Col pass, cp.async double-buffered fp16 staging (R12 exact except G now fp16).
// ---------------------------------------------------------------------------
#define SMEM_C 49152

__device__ __forceinline__ void issue_level(uint2* buf, int lvl, int i, int j0,
                                            int f4, int tg)
{
    size_t lb = (size_t)lvl * NPIX * F4 + (size_t)i * R * F4;
#pragma unroll
    for (int rr = tg; rr < 96; rr += 8) {
        int c = reflect_i(j0 - 16 + rr);
        unsigned dst = smem_u32(&buf[rr * 32 + f4]);
        const uint2* src = &g_tmph[lb + (size_t)c * F4 + f4];
        asm volatile("cp.async.ca.shared.global [%0], [%1], 8;"
                     :: "r"(dst), "l"(src) : "memory");
    }
    asm volatile("cp.async.commit_group;" ::: "memory");
}

template <int S>
__device__ __forceinline__ void col_acc(const uint2* __restrict__ buf,
                                        float bl, int base, int f4, float4* acc)
{
    constexpr GWt<S> gw{};
    float4 tmp[8];
#pragma unroll
    for (int q = 0; q < 8; q++) tmp[q] = make_float4(0.f, 0.f, 0.f, 0.f);
#pragma unroll
    for (int r = 0; r < 8 + S - 1; r++) {
        float4 v = unpack4(buf[(base + 16 - S / 2 + r) * 32 + f4]);
#pragma unroll
        for (int q = 0; q < 8; q++) {
            int jj = r - q;
            if (jj >= 0 && jj < S) {
                float k = gw.w[jj];
                tmp[q].x += k * v.x; tmp[q].y += k * v.y;
                tmp[q].z += k * v.z; tmp[q].w += k * v.w;
            }
        }
    }
#pragma unroll
    for (int q = 0; q < 8; q++) {
        acc[q].x += bl * tmp[q].x; acc[q].y += bl * tmp[q].y;
        acc[q].z += bl * tmp[q].z; acc[q].w += bl * tmp[q].w;
    }
}

__global__ void __launch_bounds__(256) k_cols(const float4* __restrict__ base4,
                                              const float* __restrict__ b_levels)
{
    extern __shared__ unsigned char smem_raw[];
    uint2* shA = (uint2*)smem_raw;             // [96][32] fp16x4
    uint2* shB = (uint2*)(smem_raw + 24576);

    int i  = blockIdx.x;
    int j0 = blockIdx.y * 64;
    int t  = threadIdx.x;
    int f4 = t & 31, tg = t >> 5;
    int base = tg * 8;

    issue_level(shA, 0, i, j0, f4, tg);        // level S=2 -> A

    float b0 = b_levels[0];
    float4 acc[8];
#pragma unroll
    for (int q = 0; q < 8; q++) {
        float4 v = base4[((size_t)i * R + (j0 + base + q)) * F4 + f4];
        acc[q] = make_float4(b0 * v.x, b0 * v.y, b0 * v.z, b0 * v.w);
    }

    issue_level(shB, 1, i, j0, f4, tg);        // S=4 -> B
    asm volatile("cp.async.wait_group 1;" ::: "memory");
    __syncthreads();
    col_acc<2 >(shA, b_levels[1], base, f4, acc);
    __syncthreads();

    issue_level(shA, 2, i, j0, f4, tg);        // S=8 -> A
    asm volatile("cp.async.wait_group 1;" ::: "memory");
    __syncthreads();
    col_acc<4 >(shB, b_levels[2], base, f4, acc);
    __syncthreads();

    issue_level(shB, 3, i, j0, f4, tg);        // S=16 -> B
    asm volatile("cp.async.wait_group 1;" ::: "memory");
    __syncthreads();
    col_acc<8 >(shA, b_levels[3], base, f4, acc);
    __syncthreads();

    issue_level(shA, 4, i, j0, f4, tg);        // S=32 -> A
    asm volatile("cp.async.wait_group 1;" ::: "memory");
    __syncthreads();
    col_acc<16>(shB, b_levels[4], base, f4, acc);
    __syncthreads();

    asm volatile("cp.async.wait_group 0;" ::: "memory");
    __syncthreads();
    col_acc<32>(shA, b_levels[5], base, f4, acc);

    // Write G as fp16 (coalesced uint2; k-pairs (2q,2q+1) = features 4q..4q+3)
#pragma unroll
    for (int q = 0; q < 8; q++)
        g_Gh[((size_t)i * R + (j0 + base + q)) * 32 + f4] = pack4(acc[q]);
}

// ---------------------------------------------------------------------------
// H = G @ W1 + b1 via fp16 MMA m16n8k16, all operands smem-resident.
// Block = 128 pixels, 512 threads / 16 warps, 2 CTAs/SM.
// smem: Gs uint[128*68]   34816 @0   (fp16 G, row stride 68 uints; reused as Hs)
//       W1s uint2[32*132] 33792 @34816
//       b1s float[128]      512 @68608.  total 69120.
// ---------------------------------------------------------------------------
#define SMEM_H 69120

__global__ void __launch_bounds__(512, 2) k_H(const float* __restrict__ b1)
{
    extern __shared__ unsigned char smem_raw[];
    unsigned* Gs  = (unsigned*)smem_raw;               // [128][68] (64 data + pad)
    uint2*    W1s = (uint2*)(smem_raw + 34816);        // [32][132]
    float*    b1s = (float*)(smem_raw + 68608);

    int blk = blockIdx.x;          // 512 blocks x 128 pixels
    int t   = threadIdx.x;

    // Stage W1 fragments (stride 132 uint2 -> conflict-free 64-bit LDS)
#pragma unroll
    for (int it = 0; it < 8; it++) {
        int task = it * 512 + t;
        int r = task >> 7;          // 0..31
        int n = task & 127;
        W1s[r * 132 + n] = g_W1h[r * 128 + n];
    }
    // Stage G tile: pixel p, half2-pair q (0..31) -> Gs[p*68 + 2q] (uint2)
#pragma unroll
    for (int it = 0; it < 8; it++) {
        int task = it * 512 + t;
        int p  = task >> 5;
        int q4 = task & 31;
        uint2 v = g_Gh[((size_t)blk * 128 + p) * 32 + q4];
        *reinterpret_cast<uint2*>(&Gs[p * 68 + 2 * q4]) = v;
    }
    if (t < 128) b1s[t] = b1[t];
    __syncthreads();

    // MMA: 128x128 = 8 m-tiles x 2 n-halves. warp = (mt = w&7, nh = w>>3).
    int w    = t >> 5;
    int lane = t & 31;
    int mt   = w & 7;
    int nh   = w >> 3;
    int g    = lane >> 2;
    int tig  = lane & 3;

    float d[8][4];
#pragma unroll
    for (int nt = 0; nt < 8; nt++)
#pragma unroll
        for (int e = 0; e < 4; e++) d[nt][e] = 0.0f;

#pragma unroll
    for (int kk = 0; kk < 8; kk++) {
        int arow = (mt * 16 + g) * 68 + kk * 8 + tig;
        unsigned a0 = Gs[arow];              // (row g,   k 16kk+2tig..+1)
        unsigned a1 = Gs[arow + 8 * 68];     // (row g+8, same)
        unsigned a2 = Gs[arow + 4];          // (row g,   k +8)
        unsigned a3 = Gs[arow + 8 * 68 + 4]; // (row g+8, k +8)
        int brow = (kk * 4 + tig) * 132 + nh * 64 + g;
#pragma unroll
        for (int nt = 0; nt < 8; nt++) {
            uint2 b = W1s[brow + nt * 8];
            mma_f16(d[nt], a0, a1, a2, a3, b.x, b.y);
        }
    }
    __syncthreads();   // all Gs reads done -> reuse as Hs

    __half2* Hs2 = (__half2*)smem_raw;   // [128][68]
    int m0 = mt * 16 + g;
#pragma unroll
    for (int nt = 0; nt < 8; nt++) {
        int n0 = nh * 64 + nt * 8 + 2 * tig;
        float bb0 = b1s[n0], bb1 = b1s[n0 + 1];
        Hs2[m0 * 68 + (n0 >> 1)]       = __floats2half2_rn(d[nt][0] + bb0,
                                                           d[nt][1] + bb1);
        Hs2[(m0 + 8) * 68 + (n0 >> 1)] = __floats2half2_rn(d[nt][2] + bb0,
                                                           d[nt][3] + bb1);
    }
    __syncthreads();

    // Coalesced fp16 H store: 128 pixels x 16 uint4 (row stride 17 uint4)
    const uint4* Hs4 = (const uint4*)smem_raw;
#pragma unroll
    for (int it = 0; it < 4; it++) {
        int task = it * 512 + t;
        int p  = task >> 4;
        int q4 = task & 15;
        g_Hh[((size_t)blk * 128 + p) * 16 + q4] = Hs4[p * 17 + q4];
    }
}

// ---------------------------------------------------------------------------
// Points: bilerp gather of fp16 H + relu + W2 + b2.  (R8/R12 exact)
// ---------------------------------------------------------------------------
__global__ void __launch_bounds__(256) k_pts(const float* __restrict__ pt,
                                             const float4* __restrict__ W2v,
                                             const float* __restrict__ b2,
                                             float4* __restrict__ out4)
{
    int t = threadIdx.x, lane = t & 31, w = t >> 5;
    int lh = lane >> 4;
    int lf = lane & 15;

    float4 w2r[8];
#pragma unroll
    for (int j = 0; j < 8; j++) w2r[j] = W2v[lf * 8 + j];
    float b20 = b2[0], b21 = b2[1], b22 = b2[2], b23 = b2[3];

    int p0 = blockIdx.x * 128 + w * 16 + lh;
#pragma unroll 2
    for (int it = 0; it < 8; it++) {
        int p = p0 + it * 2;
        float px = pt[2 * p];
        float py = pt[2 * p + 1];
        float ax = (px + 1.0f) / 2.0f * 255.0f;
        float ay = (py + 1.0f) / 2.0f * 255.0f;
        int ix = (int)ax; if (ix > 255) ix = 255;
        int iy = (int)ay; if (iy > 255) iy = 255;
        float fx = ax - (float)ix;
        float fy = ay - (float)iy;
        int ix1 = (ix + 1 > 255) ? 255 : ix + 1;
        int iy1 = (iy + 1 > 255) ? 255 : iy + 1;
        float w00 = (1.0f - fx) * (1.0f - fy);
        float w01 = (1.0f - fx) * fy;
        float w10 = fx * (1.0f - fy);
        float w11 = fx * fy;

        uint4 c00 = g_Hh[((size_t)(ix  * R + iy )) * 16 + lf];
        uint4 c01 = g_Hh[((size_t)(ix  * R + iy1)) * 16 + lf];
        uint4 c10 = g_Hh[((size_t)(ix1 * R + iy )) * 16 + lf];
        uint4 c11 = g_Hh[((size_t)(ix1 * R + iy1)) * 16 + lf];

        float v[8];
#pragma unroll
        for (int k = 0; k < 8; k++) v[k] = 0.0f;
        {
            const unsigned* cs[4] = {&c00.x, &c01.x, &c10.x, &c11.x};
            float ws[4] = {w00, w01, w10, w11};
#pragma unroll
            for (int cc = 0; cc < 4; cc++) {
                float wgt = ws[cc];
#pragma unroll
                for (int k = 0; k < 4; k++) {
                    __half2 h = *reinterpret_cast<const __half2*>(&cs[cc][k]);
                    float2 f = __half22float2(h);
                    v[2 * k]     += wgt * f.x;
                    v[2 * k + 1] += wgt * f.y;
                }
            }
        }

        float4 o = make_float4(0.f, 0.f, 0.f, 0.f);
#pragma unroll
        for (int j = 0; j < 8; j++) {
            float h = fmaxf(v[j], 0.0f);
            o.x += h * w2r[j].x; o.y += h * w2r[j].y;
            o.z += h * w2r[j].z; o.w += h * w2r[j].w;
        }

#pragma unroll
        for (int off = 8; off; off >>= 1) {
            o.x += __shfl_xor_sync(0xffffffffu, o.x, off);
            o.y += __shfl_xor_sync(0xffffffffu, o.y, off);
            o.z += __shfl_xor_sync(0xffffffffu, o.z, off);
            o.w += __shfl_xor_sync(0xffffffffu, o.w, off);
        }
        if (lf == 0)
            out4[p] = make_float4(o.x + b20, o.y + b21, o.z + b22, o.w + b23);
    }
}

// ---------------------------------------------------------------------------
extern "C" void kernel_launch(void* const* d_in, const int* in_sizes, int n_in,
                              void* d_out, int out_size) {
    const float*  pt       = (const float*)d_in[0];
    const float4* base4    = (const float4*)d_in[1];
    const float*  b_levels = (const float*)d_in[2];
    const float*  W1       = (const float*)d_in[3];
    const float*  b1       = (const float*)d_in[4];
    const float*  W2       = (const float*)d_in[5];
    const float*  b2       = (const float*)d_in[6];
    float* out             = (float*)d_out;

    cudaFuncSetAttribute(k_cols, cudaFuncAttributeMaxDynamicSharedMemorySize,
                         SMEM_C);
    cudaFuncSetAttribute(k_H, cudaFuncAttributeMaxDynamicSharedMemorySize,
                         SMEM_H);

    k_w1prep<<<16, 256>>>(W1);

    dim3 bg(256, 4);
    k_rows<<<bg, 512>>>(base4);
    k_cols<<<bg, 256, SMEM_C>>>(base4, b_levels);
    k_H<<<512, 512, SMEM_H>>>(b1);
    k_pts<<<2048, 256>>>(pt, (const float4*)W2, b2, (float4*)out);
}